// round 13
// baseline (speedup 1.0000x reference)
#include <cuda_runtime.h>
#include <math.h>

// Problem constants
#define VOCAB 50000
#define EMB   300
#define HID   256
#define BATCH 128
#define T_H   32
#define T_B   512

typedef unsigned long long ULL;

// -------- scratch (static device allocations; no cudaMalloc anywhere) --------
__device__ float g_XG_h[(size_t)BATCH * T_H * 768];   // headline x-projections [B*T, 768]
__device__ float g_XG_b[(size_t)BATCH * T_B * 768];   // body x-projections
__device__ float g_out_h[(size_t)BATCH * T_H * HID];  // headline layer-0 outputs
__device__ float g_out_b[(size_t)BATCH * T_B * HID];  // body layer-0 outputs
__device__ float g_hcat [(size_t)BATCH * 512];        // [h_head | h_body] final states

// ---- packed f32x2 helpers (fp32-exact) ----
__device__ __forceinline__ void fma2(ULL& d, ULL a, ULL b) {
    asm("fma.rn.f32x2 %0, %1, %2, %0;" : "+l"(d) : "l"(a), "l"(b));
}
__device__ __forceinline__ ULL add2(ULL a, ULL b) {
    ULL d; asm("add.rn.f32x2 %0, %1, %2;" : "=l"(d) : "l"(a), "l"(b)); return d;
}
__device__ __forceinline__ ULL dup2(float x) {
    ULL r; asm("mov.b64 %0, {%1, %1};" : "=l"(r) : "f"(x)); return r;
}
__device__ __forceinline__ ULL packf2(float a, float b) {
    ULL r; asm("mov.b64 %0, {%1, %2};" : "=l"(r) : "f"(a), "f"(b)); return r;
}
__device__ __forceinline__ void unpack2(ULL v, float& a, float& b) {
    asm("mov.b64 {%0, %1}, %2;" : "=f"(a), "=f"(b) : "l"(v));
}

// ---- cluster / DSMEM helpers ----
__device__ __forceinline__ void cluster_sync_() {
    asm volatile("barrier.cluster.arrive.aligned;" ::: "memory");
    asm volatile("barrier.cluster.wait.aligned;" ::: "memory");
}
__device__ __forceinline__ unsigned s2u(const void* p) {
    return (unsigned)__cvta_generic_to_shared(p);
}
__device__ __forceinline__ unsigned mapa_sh(unsigned local, unsigned rank) {
    unsigned r;
    asm("mapa.shared::cluster.u32 %0, %1, %2;" : "=r"(r) : "r"(local), "r"(rank));
    return r;
}
__device__ __forceinline__ void st_dsmem_u64(unsigned addr, ULL v) {
    asm volatile("st.shared::cluster.u64 [%0], %1;" :: "r"(addr), "l"(v) : "memory");
}

// ============================================================================
// Generic SGEMM (unchanged): C[M,N] = A[M,K] @ B[K,N] + bias, row-major.
// ============================================================================
template <bool GATHER>
__global__ __launch_bounds__(256)
void sgemm_kernel(const float* __restrict__ A, const int* __restrict__ ids, int lda,
                  const float* __restrict__ Bm, int ldb,
                  const float* __restrict__ bias,
                  float* __restrict__ C, int ldc, int coff,
                  int M, int N, int K)
{
    const int BM = 128, BN = 64, BK = 8;
    __shared__ float As[BK][BM];
    __shared__ float Bs[BK][BN];

    int nbn = N / BN;
    int bm = blockIdx.x / nbn;
    int bn = blockIdx.x % nbn;
    int tid = threadIdx.x;
    int tx = tid & 15;
    int ty = tid >> 4;

    float acc[8][4];
#pragma unroll
    for (int i = 0; i < 8; i++)
#pragma unroll
        for (int j = 0; j < 4; j++) acc[i][j] = 0.0f;

    int ar = tid >> 1;
    int ak = (tid & 1) * 4;
    int arow = bm * BM + ar;
    const float* arow_ptr;
    if (GATHER) arow_ptr = A + (size_t)ids[arow] * lda;
    else        arow_ptr = A + (size_t)arow * lda;

    int bkr = tid >> 5;
    int bc  = (tid & 31) * 2;
    const float* bptr = Bm + (size_t)bn * BN + bc;

    for (int k0 = 0; k0 < K; k0 += BK) {
        float4 av = make_float4(0.f, 0.f, 0.f, 0.f);
        if (k0 + ak < K) av = *(const float4*)(arow_ptr + k0 + ak);
        float2 bv = make_float2(0.f, 0.f);
        if (k0 + bkr < K) bv = *(const float2*)(bptr + (size_t)(k0 + bkr) * ldb);

        __syncthreads();
        As[ak + 0][ar] = av.x; As[ak + 1][ar] = av.y;
        As[ak + 2][ar] = av.z; As[ak + 3][ar] = av.w;
        Bs[bkr][bc] = bv.x; Bs[bkr][bc + 1] = bv.y;
        __syncthreads();

#pragma unroll
        for (int kk = 0; kk < BK; kk++) {
            float4 b4 = *(const float4*)&Bs[kk][tx * 4];
            float4 a0 = *(const float4*)&As[kk][ty * 8];
            float4 a1 = *(const float4*)&As[kk][ty * 8 + 4];
            float arr[8] = {a0.x, a0.y, a0.z, a0.w, a1.x, a1.y, a1.z, a1.w};
            float brr[4] = {b4.x, b4.y, b4.z, b4.w};
#pragma unroll
            for (int i = 0; i < 8; i++)
#pragma unroll
                for (int j = 0; j < 4; j++)
                    acc[i][j] += arr[i] * brr[j];
        }
    }

    float4 bb = *(const float4*)&bias[bn * BN + tx * 4];
    float bbr[4] = {bb.x, bb.y, bb.z, bb.w};
#pragma unroll
    for (int i = 0; i < 8; i++) {
        int row = bm * BM + ty * 8 + i;
        float4 o;
        o.x = acc[i][0] + bbr[0];
        o.y = acc[i][1] + bbr[1];
        o.z = acc[i][2] + bbr[2];
        o.w = acc[i][3] + bbr[3];
        *(float4*)(C + (size_t)row * ldc + coff + bn * BN + tx * 4) = o;
    }
}

// ============================================================================
// GRU scan, round 13: cluster(2) + DSMEM (as R12) + smem weight cache +
// col-pair packed mainloops.
//   role 0: r-gates (cols 0..255) + cand cols [0,128)
//   role 1: u-gates (cols 256..511) + cand cols [128,256)
// Smem cache: gate weights k in [0,128) (128KB), cand weights k in [0,96)
// (48KB); remainder streamed from L2 each step (208KB vs 384KB).
// Accumulators are column-pair packed: weight word (w_c0,w_c1) feeds FFMA2
// directly against pre-duplicated h (h,h) -> 7 instr / 8 MAC.
// Dynamic smem total: 225,296 B.
// ============================================================================
struct ScanArgs {
    const float* XG;
    const float* Wgh;   // [256,512] k-major h-part of gate weights
    const float* Wch;   // [256,256] k-major h-part of cand weights
    const int*   ids;
    float*       outs;
    float*       hfin;
    int          hoff;
    int          T;
};

// dynamic smem layout (ULL units)
#define U_WG   0        // ULL [128][128]  gate cache  (16384)
#define U_WC   16384    // ULL [96][64]    cand cache  (6144)
#define U_PART 22528    // ULL partials: gate [4][128][4] / cand [8][64][4] (2048)
#define U_HD   24576    // ULL [256][4]   h duplicated (1024)
#define U_RH   25600    // ULL [256][4]   r*h duplicated (1024)
#define U_US   26624    // float [2][4][256] u gates, double-buffered (1024 ULL)
#define U_CS   27648    // float [4][256] candidate (512 ULL)
#define U_SV   28160    // int [4]
#define SMEM_SCAN_BYTES 225408

__global__ void __cluster_dims__(2, 1, 1) __launch_bounds__(512)
gru_scan_cluster(ScanArgs body, ScanArgs head)
{
    extern __shared__ ULL dynsm[];
    ULL*   WG  = dynsm + U_WG;
    ULL*   WC  = dynsm + U_WC;
    ULL*   PART= dynsm + U_PART;
    ULL*   HD  = dynsm + U_HD;
    ULL*   RH  = dynsm + U_RH;
    float* USf = (float*)(dynsm + U_US);
    float* CSf = (float*)(dynsm + U_CS);
    int*   sv  = (int*)(dynsm + U_SV);

    const int bx = blockIdx.x;
    ScanArgs A = (bx < 64) ? body : head;
    const int role = bx & 1;
    const unsigned peer = 1u - (unsigned)role;
    const int pgl = (bx & 63) >> 1;
    const int b0  = pgl * 4;
    const int tid = threadIdx.x;
    const int T = A.T;

    const int cb  = role << 8;          // gate col base (0 or 256)
    const int cbc = role << 7;          // cand col base (0 or 128)

    // init h = 0
    for (int i = tid; i < 1024; i += 512) HD[i] = 0ull;

    // ---- preload weight caches ----
    for (int i = tid; i < 128 * 128; i += 512) {       // gate k<128
        int k = i >> 7, cp = i & 127;
        WG[i] = *(const ULL*)(A.Wgh + (size_t)k * 512 + cb + 2 * cp);
    }
    for (int i = tid; i < 96 * 64; i += 512) {         // cand k<96
        int k = i >> 6, cp = i & 63;
        WC[i] = *(const ULL*)(A.Wch + (size_t)k * 256 + cbc + 2 * cp);
    }
    __syncthreads();

    // mainloop mappings
    const int ow = tid & 127;           // gate colpair owner (2 cols)
    const int ks = tid >> 7;            // gate k-split 0..3 (64 k each)
    const int oc = tid & 63;            // cand colpair owner
    const int kc = tid >> 6;            // cand k-split 0..7 (32 k each)
    // combine mappings
    const int owc = tid >> 2, rg = tid & 3;            // gate: 128 cp x 4 rows
    const int oc2 = (tid & 255) >> 2, rc = tid & 3;    // cand: 64 cp x 4 rows

    // peer DSMEM base addresses
    const unsigned rh_peer = mapa_sh(s2u(RH),  peer);
    const unsigned us_peer = mapa_sh(s2u(USf), peer);
    const unsigned cs_peer = mapa_sh(s2u(CSf), peer);

    cluster_sync_();

    for (int t = 0; t < T; t++) {
        const int buf = t & 1;

        // ---- prefetch x-parts + validity ----
        const float2 xg2 = *(const float2*)(A.XG +
            (size_t)((b0 + rg) * T + t) * 768 + cb + 2 * owc);
        float2 xc2 = make_float2(0.f, 0.f);
        if (tid < 256)
            xc2 = *(const float2*)(A.XG +
                (size_t)((b0 + rc) * T + t) * 768 + 512 + cbc + 2 * oc2);
        if (tid < 4) sv[tid] = A.ids[(b0 + tid) * T + t];

        // ---- gate mainloop: colpair ow, rows 0..3, k in [64ks, 64ks+64) ----
        {
            ULL a0 = 0ull, a1 = 0ull, a2 = 0ull, a3 = 0ull;
            const ULL* hd = HD + (ks * 64) * 4;
            if (ks < 2) {
                const ULL* wp = WG + (size_t)(ks * 64) * 128 + ow;
#pragma unroll 16
                for (int kk = 0; kk < 64; kk++) {
                    ULL w2 = wp[(size_t)kk * 128];
                    fma2(a0, w2, hd[kk * 4 + 0]); fma2(a1, w2, hd[kk * 4 + 1]);
                    fma2(a2, w2, hd[kk * 4 + 2]); fma2(a3, w2, hd[kk * 4 + 3]);
                }
            } else {
                const float* gp = A.Wgh + (size_t)(ks * 64) * 512 + cb + 2 * ow;
#pragma unroll 16
                for (int kk = 0; kk < 64; kk++) {
                    ULL w2 = *(const ULL*)(gp + (size_t)kk * 512);
                    fma2(a0, w2, hd[kk * 4 + 0]); fma2(a1, w2, hd[kk * 4 + 1]);
                    fma2(a2, w2, hd[kk * 4 + 2]); fma2(a3, w2, hd[kk * 4 + 3]);
                }
            }
            ULL* dst = PART + (size_t)(ks * 128 + ow) * 4;
            dst[0] = a0; dst[1] = a1; dst[2] = a2; dst[3] = a3;
        }
        __syncthreads();

        // ---- gate combine + sigmoid; role0 -> rh (local+peer), role1 -> u ----
        {
            ULL s = add2(add2(PART[(0 * 128 + owc) * 4 + rg],
                              PART[(1 * 128 + owc) * 4 + rg]),
                         add2(PART[(2 * 128 + owc) * 4 + rg],
                              PART[(3 * 128 + owc) * 4 + rg]));
            float s0, s1; unpack2(s, s0, s1);
            float g0 = 1.f / (1.f + expf(-(s0 + xg2.x)));
            float g1 = 1.f / (1.f + expf(-(s1 + xg2.y)));
            if (role == 0) {
                float h0, hx, h1;
                unpack2(HD[(2 * owc) * 4 + rg], h0, hx);
                unpack2(HD[(2 * owc + 1) * 4 + rg], h1, hx);
                ULL d0 = dup2(g0 * h0), d1 = dup2(g1 * h1);
                RH[(2 * owc) * 4 + rg]     = d0;
                RH[(2 * owc + 1) * 4 + rg] = d1;
                st_dsmem_u64(rh_peer + (unsigned)((2 * owc) * 4 + rg) * 8u, d0);
                st_dsmem_u64(rh_peer + (unsigned)((2 * owc + 1) * 4 + rg) * 8u, d1);
            } else {
                ULL u = packf2(g0, g1);
                *(ULL*)&USf[(buf * 4 + rg) * 256 + 2 * owc] = u;
                st_dsmem_u64(us_peer + (unsigned)((buf * 4 + rg) * 256 + 2 * owc) * 4u, u);
            }
        }
        cluster_sync_();   // S1: rh visible in both CTAs

        // ---- cand mainloop: colpair oc, rows 0..3, k in [32kc, 32kc+32) ----
        {
            ULL a0 = 0ull, a1 = 0ull, a2 = 0ull, a3 = 0ull;
            const ULL* rh = RH + (kc * 32) * 4;
            if (kc < 3) {
                const ULL* wp = WC + (size_t)(kc * 32) * 64 + oc;
#pragma unroll 16
                for (int kk = 0; kk < 32; kk++) {
                    ULL w2 = wp[(size_t)kk * 64];
                    fma2(a0, w2, rh[kk * 4 + 0]); fma2(a1, w2, rh[kk * 4 + 1]);
                    fma2(a2, w2, rh[kk * 4 + 2]); fma2(a3, w2, rh[kk * 4 + 3]);
                }
            } else {
                const float* gp = A.Wch + (size_t)(kc * 32) * 256 + cbc + 2 * oc;
#pragma unroll 16
                for (int kk = 0; kk < 32; kk++) {
                    ULL w2 = *(const ULL*)(gp + (size_t)kk * 256);
                    fma2(a0, w2, rh[kk * 4 + 0]); fma2(a1, w2, rh[kk * 4 + 1]);
                    fma2(a2, w2, rh[kk * 4 + 2]); fma2(a3, w2, rh[kk * 4 + 3]);
                }
            }
            ULL* dst = PART + (size_t)(kc * 64 + oc) * 4;
            dst[0] = a0; dst[1] = a1; dst[2] = a2; dst[3] = a3;
        }
        __syncthreads();

        // ---- cand combine + tanh (tid < 256) ----
        if (tid < 256) {
            ULL s = add2(add2(add2(PART[(0 * 64 + oc2) * 4 + rc],
                                   PART[(1 * 64 + oc2) * 4 + rc]),
                              add2(PART[(2 * 64 + oc2) * 4 + rc],
                                   PART[(3 * 64 + oc2) * 4 + rc])),
                         add2(add2(PART[(4 * 64 + oc2) * 4 + rc],
                                   PART[(5 * 64 + oc2) * 4 + rc]),
                              add2(PART[(6 * 64 + oc2) * 4 + rc],
                                   PART[(7 * 64 + oc2) * 4 + rc])));
            float s0, s1; unpack2(s, s0, s1);
            ULL c = packf2(tanhf(s0 + xc2.x), tanhf(s1 + xc2.y));
            int gc = cbc + 2 * oc2;
            *(ULL*)&CSf[rc * 256 + gc] = c;
            st_dsmem_u64(cs_peer + (unsigned)(rc * 256 + gc) * 4u, c);
        }
        cluster_sync_();   // S2: c complete in both CTAs

        // ---- update (replicated; bit-identical inputs) ----
        {
#pragma unroll
            for (int p = 0; p < 2; p++) {
                int col = tid & 255;
                int r = (tid >> 8) + 2 * p;
                float u = USf[(buf * 4 + r) * 256 + col];
                float c = CSf[r * 256 + col];
                float h0, hx; unpack2(HD[col * 4 + r], h0, hx);
                float hn = u * h0 + (1.f - u) * c;
                bool v = sv[r] != 0;
                float keep = v ? hn : h0;
                HD[col * 4 + r] = dup2(keep);
                if (A.outs && (col >> 7) == role)
                    A.outs[(size_t)((b0 + r) * T + t) * 256 + col] = v ? hn : 0.f;
            }
        }
        __syncthreads();   // HD ready for next step
    }

    // ---- final hidden state (own column half) ----
    if (A.hfin) {
#pragma unroll
        for (int p = 0; p < 2; p++) {
            int col = tid & 255;
            int r = (tid >> 8) + 2 * p;
            if ((col >> 7) == role) {
                float h0, hx; unpack2(HD[col * 4 + r], h0, hx);
                A.hfin[(size_t)(b0 + r) * 512 + A.hoff + col] = h0;
            }
        }
    }
    cluster_sync_();   // no CTA exits while peer may still DSMEM-target it
}

// ============================================================================
// Final projection: out[128,4] = [h_head | h_body] @ W_pred + b_pred
// ============================================================================
__global__ void final_pred_kernel(const float* __restrict__ Wp,
                                  const float* __restrict__ bp,
                                  float* __restrict__ out)
{
    int b = threadIdx.x;
    float a0 = bp[0], a1 = bp[1], a2 = bp[2], a3 = bp[3];
    const float* h = g_hcat + (size_t)b * 512;
#pragma unroll 8
    for (int j = 0; j < 512; j++) {
        float hv = h[j];
        float4 w = *(const float4*)(Wp + j * 4);
        a0 += hv * w.x; a1 += hv * w.y; a2 += hv * w.z; a3 += hv * w.w;
    }
    *(float4*)(out + b * 4) = make_float4(a0, a1, a2, a3);
}

// ============================================================================
// Launch
// ============================================================================
extern "C" void kernel_launch(void* const* d_in, const int* in_sizes, int n_in,
                              void* d_out, int out_size)
{
    (void)n_in; (void)out_size;

    const int*   ids_h  = (const int*)d_in[0];
    const int*   ids_b  = (const int*)d_in[1];
    const float* emb    = (const float*)d_in[2];

    const float *hd0_Wg, *hd0_bg, *hd0_Wc, *hd0_bc;
    const float *hd1_Wg, *hd1_bg, *hd1_Wc, *hd1_bc;
    const float *bd0_Wg, *bd0_bg, *bd0_Wc, *bd0_bc;
    const float *bd1_Wg, *bd1_bg, *bd1_Wc, *bd1_bc;
    const float *W_pred, *b_pred;

    if (in_sizes[3] == (2 * HID) * 4 && in_sizes[4] == 4) {
        W_pred = (const float*)d_in[3];
        b_pred = (const float*)d_in[4];
        hd0_Wg = (const float*)d_in[5];  hd0_bg = (const float*)d_in[6];
        hd0_Wc = (const float*)d_in[7];  hd0_bc = (const float*)d_in[8];
        hd1_Wg = (const float*)d_in[9];  hd1_bg = (const float*)d_in[10];
        hd1_Wc = (const float*)d_in[11]; hd1_bc = (const float*)d_in[12];
        bd0_Wg = (const float*)d_in[13]; bd0_bg = (const float*)d_in[14];
        bd0_Wc = (const float*)d_in[15]; bd0_bc = (const float*)d_in[16];
        bd1_Wg = (const float*)d_in[17]; bd1_bg = (const float*)d_in[18];
        bd1_Wc = (const float*)d_in[19]; bd1_bc = (const float*)d_in[20];
    } else {
        hd0_Wg = (const float*)d_in[3];  hd0_bg = (const float*)d_in[4];
        hd0_Wc = (const float*)d_in[5];  hd0_bc = (const float*)d_in[6];
        hd1_Wg = (const float*)d_in[7];  hd1_bg = (const float*)d_in[8];
        hd1_Wc = (const float*)d_in[9];  hd1_bc = (const float*)d_in[10];
        bd0_Wg = (const float*)d_in[11]; bd0_bg = (const float*)d_in[12];
        bd0_Wc = (const float*)d_in[13]; bd0_bc = (const float*)d_in[14];
        bd1_Wg = (const float*)d_in[15]; bd1_bg = (const float*)d_in[16];
        bd1_Wc = (const float*)d_in[17]; bd1_bc = (const float*)d_in[18];
        W_pred = (const float*)d_in[19];
        b_pred = (const float*)d_in[20];
    }

    float* out = (float*)d_out;

    float *XG_h, *XG_b, *out_h, *out_b, *hcat;
    cudaGetSymbolAddress((void**)&XG_h, g_XG_h);
    cudaGetSymbolAddress((void**)&XG_b, g_XG_b);
    cudaGetSymbolAddress((void**)&out_h, g_out_h);
    cudaGetSymbolAddress((void**)&out_b, g_out_b);
    cudaGetSymbolAddress((void**)&hcat, g_hcat);

    // allow 225 KB dynamic smem for the scan kernel (idempotent)
    cudaFuncSetAttribute(gru_scan_cluster,
                         cudaFuncAttributeMaxDynamicSharedMemorySize,
                         SMEM_SCAN_BYTES);

    const int Mh = BATCH * T_H;
    const int Mb = BATCH * T_B;

    // ---- Layer-0 x-projections (embedding gather fused) ----
    sgemm_kernel<true><<<(Mh / 128) * (512 / 64), 256>>>(
        emb, ids_h, EMB, hd0_Wg, 512, hd0_bg, XG_h, 768, 0,   Mh, 512, EMB);
    sgemm_kernel<true><<<(Mh / 128) * (256 / 64), 256>>>(
        emb, ids_h, EMB, hd0_Wc, 256, hd0_bc, XG_h, 768, 512, Mh, 256, EMB);
    sgemm_kernel<true><<<(Mb / 128) * (512 / 64), 256>>>(
        emb, ids_b, EMB, bd0_Wg, 512, bd0_bg, XG_b, 768, 0,   Mb, 512, EMB);
    sgemm_kernel<true><<<(Mb / 128) * (256 / 64), 256>>>(
        emb, ids_b, EMB, bd0_Wc, 256, bd0_bc, XG_b, 768, 512, Mb, 256, EMB);

    // ---- Layer-0 scan ----
    {
        ScanArgs body = { XG_b, bd0_Wg + (size_t)EMB * 512, bd0_Wc + (size_t)EMB * 256,
                          ids_b, out_b, nullptr, 0, T_B };
        ScanArgs head = { XG_h, hd0_Wg + (size_t)EMB * 512, hd0_Wc + (size_t)EMB * 256,
                          ids_h, out_h, nullptr, 0, T_H };
        gru_scan_cluster<<<128, 512, SMEM_SCAN_BYTES>>>(body, head);
    }

    // ---- Layer-1 x-projections ----
    sgemm_kernel<false><<<(Mh / 128) * (512 / 64), 256>>>(
        out_h, nullptr, HID, hd1_Wg, 512, hd1_bg, XG_h, 768, 0,   Mh, 512, HID);
    sgemm_kernel<false><<<(Mh / 128) * (256 / 64), 256>>>(
        out_h, nullptr, HID, hd1_Wc, 256, hd1_bc, XG_h, 768, 512, Mh, 256, HID);
    sgemm_kernel<false><<<(Mb / 128) * (512 / 64), 256>>>(
        out_b, nullptr, HID, bd1_Wg, 512, bd1_bg, XG_b, 768, 0,   Mb, 512, HID);
    sgemm_kernel<false><<<(Mb / 128) * (256 / 64), 256>>>(
        out_b, nullptr, HID, bd1_Wc, 256, bd1_bc, XG_b, 768, 512, Mb, 256, HID);

    // ---- Layer-1 scan ----
    {
        ScanArgs body = { XG_b, bd1_Wg + (size_t)HID * 512, bd1_Wc + (size_t)HID * 256,
                          ids_b, nullptr, hcat, 256, T_B };
        ScanArgs head = { XG_h, hd1_Wg + (size_t)HID * 512, hd1_Wc + (size_t)HID * 256,
                          ids_h, nullptr, hcat, 0, T_H };
        gru_scan_cluster<<<128, 512, SMEM_SCAN_BYTES>>>(body, head);
    }

    // ---- Final projection ----
    final_pred_kernel<<<1, 128>>>(W_pred, b_pred, out);
}

// round 14
// speedup vs baseline: 1.1055x; 1.1055x over previous
#include <cuda_runtime.h>
#include <math.h>

// Problem constants
#define VOCAB 50000
#define EMB   300
#define HID   256
#define BATCH 128
#define T_H   32
#define T_B   512

typedef unsigned long long ULL;

// -------- scratch (static device allocations; no cudaMalloc anywhere) --------
__device__ float g_XG_h[(size_t)BATCH * T_H * 768];   // headline x-projections [B*T, 768]
__device__ float g_XG_b[(size_t)BATCH * T_B * 768];   // body x-projections
__device__ float g_out_h[(size_t)BATCH * T_H * HID];  // headline layer-0 outputs
__device__ float g_out_b[(size_t)BATCH * T_B * HID];  // body layer-0 outputs
__device__ float g_hcat [(size_t)BATCH * 512];        // [h_head | h_body] final states

// ---- packed f32x2 helpers (fp32-exact) ----
__device__ __forceinline__ void fma2(ULL& d, ULL a, ULL b) {
    asm("fma.rn.f32x2 %0, %1, %2, %0;" : "+l"(d) : "l"(a), "l"(b));
}
__device__ __forceinline__ ULL add2(ULL a, ULL b) {
    ULL d; asm("add.rn.f32x2 %0, %1, %2;" : "=l"(d) : "l"(a), "l"(b)); return d;
}
__device__ __forceinline__ ULL dup2(float x) {
    ULL r; asm("mov.b64 %0, {%1, %1};" : "=l"(r) : "f"(x)); return r;
}
__device__ __forceinline__ ULL packf2(float a, float b) {
    ULL r; asm("mov.b64 %0, {%1, %2};" : "=l"(r) : "f"(a), "f"(b)); return r;
}
__device__ __forceinline__ void unpack2(ULL v, float& a, float& b) {
    asm("mov.b64 {%0, %1}, %2;" : "=f"(a), "=f"(b) : "l"(v));
}

// ---- cluster / DSMEM helpers ----
__device__ __forceinline__ void cluster_sync_() {
    asm volatile("barrier.cluster.arrive.aligned;" ::: "memory");
    asm volatile("barrier.cluster.wait.aligned;" ::: "memory");
}
__device__ __forceinline__ void cluster_arrive_() {
    asm volatile("barrier.cluster.arrive.aligned;" ::: "memory");
}
__device__ __forceinline__ void cluster_wait_() {
    asm volatile("barrier.cluster.wait.aligned;" ::: "memory");
}
__device__ __forceinline__ unsigned s2u(const void* p) {
    return (unsigned)__cvta_generic_to_shared(p);
}
__device__ __forceinline__ unsigned mapa_sh(unsigned local, unsigned rank) {
    unsigned r;
    asm("mapa.shared::cluster.u32 %0, %1, %2;" : "=r"(r) : "r"(local), "r"(rank));
    return r;
}
__device__ __forceinline__ void st_dsmem_u64(unsigned addr, ULL v) {
    asm volatile("st.shared::cluster.u64 [%0], %1;" :: "r"(addr), "l"(v) : "memory");
}

// ============================================================================
// Generic SGEMM (unchanged): C[M,N] = A[M,K] @ B[K,N] + bias, row-major.
// ============================================================================
template <bool GATHER>
__global__ __launch_bounds__(256)
void sgemm_kernel(const float* __restrict__ A, const int* __restrict__ ids, int lda,
                  const float* __restrict__ Bm, int ldb,
                  const float* __restrict__ bias,
                  float* __restrict__ C, int ldc, int coff,
                  int M, int N, int K)
{
    const int BM = 128, BN = 64, BK = 8;
    __shared__ float As[BK][BM];
    __shared__ float Bs[BK][BN];

    int nbn = N / BN;
    int bm = blockIdx.x / nbn;
    int bn = blockIdx.x % nbn;
    int tid = threadIdx.x;
    int tx = tid & 15;
    int ty = tid >> 4;

    float acc[8][4];
#pragma unroll
    for (int i = 0; i < 8; i++)
#pragma unroll
        for (int j = 0; j < 4; j++) acc[i][j] = 0.0f;

    int ar = tid >> 1;
    int ak = (tid & 1) * 4;
    int arow = bm * BM + ar;
    const float* arow_ptr;
    if (GATHER) arow_ptr = A + (size_t)ids[arow] * lda;
    else        arow_ptr = A + (size_t)arow * lda;

    int bkr = tid >> 5;
    int bc  = (tid & 31) * 2;
    const float* bptr = Bm + (size_t)bn * BN + bc;

    for (int k0 = 0; k0 < K; k0 += BK) {
        float4 av = make_float4(0.f, 0.f, 0.f, 0.f);
        if (k0 + ak < K) av = *(const float4*)(arow_ptr + k0 + ak);
        float2 bv = make_float2(0.f, 0.f);
        if (k0 + bkr < K) bv = *(const float2*)(bptr + (size_t)(k0 + bkr) * ldb);

        __syncthreads();
        As[ak + 0][ar] = av.x; As[ak + 1][ar] = av.y;
        As[ak + 2][ar] = av.z; As[ak + 3][ar] = av.w;
        Bs[bkr][bc] = bv.x; Bs[bkr][bc + 1] = bv.y;
        __syncthreads();

#pragma unroll
        for (int kk = 0; kk < BK; kk++) {
            float4 b4 = *(const float4*)&Bs[kk][tx * 4];
            float4 a0 = *(const float4*)&As[kk][ty * 8];
            float4 a1 = *(const float4*)&As[kk][ty * 8 + 4];
            float arr[8] = {a0.x, a0.y, a0.z, a0.w, a1.x, a1.y, a1.z, a1.w};
            float brr[4] = {b4.x, b4.y, b4.z, b4.w};
#pragma unroll
            for (int i = 0; i < 8; i++)
#pragma unroll
                for (int j = 0; j < 4; j++)
                    acc[i][j] += arr[i] * brr[j];
        }
    }

    float4 bb = *(const float4*)&bias[bn * BN + tx * 4];
    float bbr[4] = {bb.x, bb.y, bb.z, bb.w};
#pragma unroll
    for (int i = 0; i < 8; i++) {
        int row = bm * BM + ty * 8 + i;
        float4 o;
        o.x = acc[i][0] + bbr[0];
        o.y = acc[i][1] + bbr[1];
        o.z = acc[i][2] + bbr[2];
        o.w = acc[i][3] + bbr[3];
        *(float4*)(C + (size_t)row * ldc + coff + bn * BN + tx * 4) = o;
    }
}

// ============================================================================
// GRU scan, round 14: R12 cluster(2)+DSMEM structure, col-pair packed FFMA2
// mainloops (7 instr / 8 MAC), NO smem weight cache (preserve L1D carveout),
// split cluster arrive/wait at S1 with cand-weight preload.
//   role 0: r-gates (cols 0..255) + cand cols [0,128)
//   role 1: u-gates (cols 256..511) + cand cols [128,256)
// Static smem ~44 KB. Grid = 128 blocks (64 clusters): [0,64) body, [64,128) head.
// ============================================================================
struct ScanArgs {
    const float* XG;
    const float* Wgh;   // [256,512] k-major h-part of gate weights
    const float* Wch;   // [256,256] k-major h-part of cand weights
    const int*   ids;
    float*       outs;
    float*       hfin;
    int          hoff;
    int          T;
};

__global__ void __cluster_dims__(2, 1, 1) __launch_bounds__(512)
gru_scan_cluster(ScanArgs body, ScanArgs head)
{
    __shared__ ULL   PART[2048];        // gate [4][128][4] / cand [8][64][4]  16KB
    __shared__ ULL   HD[256][4];        // h duplicated (h,h) per (k,row)       8KB
    __shared__ ULL   RH[256][4];        // r*h duplicated                       8KB
    __shared__ float USf[2][4][256];    // u gates, double-buffered             8KB
    __shared__ float CSf[4][256];       // candidate                            4KB
    __shared__ int   sv[4];

    const int bx = blockIdx.x;
    ScanArgs A = (bx < 64) ? body : head;
    const int role = bx & 1;
    const unsigned peer = 1u - (unsigned)role;
    const int pgl = (bx & 63) >> 1;
    const int b0  = pgl * 4;
    const int tid = threadIdx.x;
    const int T = A.T;

    const int cb  = role << 8;          // gate col base (0 or 256)
    const int cbc = role << 7;          // cand col base (0 or 128)

    // init h = 0
    for (int i = tid; i < 1024; i += 512) ((ULL*)HD)[i] = 0ull;
    __syncthreads();

    // mainloop mappings
    const int ow = tid & 127;           // gate colpair owner (2 cols)
    const int ks = tid >> 7;            // gate k-split 0..3 (64 k each)
    const int oc = tid & 63;            // cand colpair owner
    const int kc = tid >> 6;            // cand k-split 0..7 (32 k each)
    // combine mappings
    const int owc = tid >> 2, rg = tid & 3;            // gate: 128 cp x 4 rows
    const int oc2 = (tid & 255) >> 2, rc = tid & 3;    // cand: 64 cp x 4 rows

    const float* __restrict__ wg_ptr = A.Wgh + (size_t)(ks * 64) * 512 + cb + 2 * ow;
    const float* __restrict__ wc_ptr = A.Wch + (size_t)(kc * 32) * 256 + cbc + 2 * oc;

    // peer DSMEM base addresses
    const unsigned rh_peer = mapa_sh(s2u(RH),  peer);
    const unsigned us_peer = mapa_sh(s2u(USf), peer);
    const unsigned cs_peer = mapa_sh(s2u(CSf), peer);

    cluster_sync_();

    for (int t = 0; t < T; t++) {
        const int buf = t & 1;

        // ---- prefetch x-parts + validity ----
        const float2 xg2 = *(const float2*)(A.XG +
            (size_t)((b0 + rg) * T + t) * 768 + cb + 2 * owc);
        float2 xc2 = make_float2(0.f, 0.f);
        if (tid < 256)
            xc2 = *(const float2*)(A.XG +
                (size_t)((b0 + rc) * T + t) * 768 + 512 + cbc + 2 * oc2);
        if (tid < 4) sv[tid] = A.ids[(b0 + tid) * T + t];

        // ---- gate mainloop: colpair ow, rows 0..3, k in [64ks, 64ks+64) ----
        {
            ULL a0 = 0ull, a1 = 0ull, a2 = 0ull, a3 = 0ull;
            const ULL* hd = &HD[ks * 64][0];
#pragma unroll 16
            for (int kk = 0; kk < 64; kk++) {
                ULL w2 = *(const ULL*)(wg_ptr + (size_t)kk * 512);
                fma2(a0, w2, hd[kk * 4 + 0]); fma2(a1, w2, hd[kk * 4 + 1]);
                fma2(a2, w2, hd[kk * 4 + 2]); fma2(a3, w2, hd[kk * 4 + 3]);
            }
            ULL* dst = PART + (size_t)(ks * 128 + ow) * 4;
            dst[0] = a0; dst[1] = a1; dst[2] = a2; dst[3] = a3;
        }
        __syncthreads();

        // ---- gate combine + sigmoid; role0 -> rh (local+peer), role1 -> u ----
        {
            ULL s = add2(add2(PART[(0 * 128 + owc) * 4 + rg],
                              PART[(1 * 128 + owc) * 4 + rg]),
                         add2(PART[(2 * 128 + owc) * 4 + rg],
                              PART[(3 * 128 + owc) * 4 + rg]));
            float s0, s1; unpack2(s, s0, s1);
            float g0 = 1.f / (1.f + expf(-(s0 + xg2.x)));
            float g1 = 1.f / (1.f + expf(-(s1 + xg2.y)));
            if (role == 0) {
                float h0, hx, h1;
                unpack2(HD[2 * owc][rg], h0, hx);
                unpack2(HD[2 * owc + 1][rg], h1, hx);
                ULL d0 = dup2(g0 * h0), d1 = dup2(g1 * h1);
                RH[2 * owc][rg]     = d0;
                RH[2 * owc + 1][rg] = d1;
                st_dsmem_u64(rh_peer + (unsigned)((2 * owc) * 4 + rg) * 8u, d0);
                st_dsmem_u64(rh_peer + (unsigned)((2 * owc + 1) * 4 + rg) * 8u, d1);
            } else {
                ULL u = packf2(g0, g1);
                *(ULL*)&USf[buf][rg][2 * owc] = u;
                st_dsmem_u64(us_peer + (unsigned)((buf * 4 + rg) * 256 + 2 * owc) * 4u, u);
            }
        }
        // ---- S1 split: arrive, preload peer-independent cand weights, wait ----
        cluster_arrive_();
        ULL wpre[8];
#pragma unroll
        for (int kk = 0; kk < 8; kk++)
            wpre[kk] = *(const ULL*)(wc_ptr + (size_t)kk * 256);
        cluster_wait_();   // S1: rh visible in both CTAs

        // ---- cand mainloop: colpair oc, rows 0..3, k in [32kc, 32kc+32) ----
        {
            ULL a0 = 0ull, a1 = 0ull, a2 = 0ull, a3 = 0ull;
            const ULL* rh = &RH[kc * 32][0];
#pragma unroll
            for (int kk = 0; kk < 8; kk++) {
                ULL w2 = wpre[kk];
                fma2(a0, w2, rh[kk * 4 + 0]); fma2(a1, w2, rh[kk * 4 + 1]);
                fma2(a2, w2, rh[kk * 4 + 2]); fma2(a3, w2, rh[kk * 4 + 3]);
            }
#pragma unroll 12
            for (int kk = 8; kk < 32; kk++) {
                ULL w2 = *(const ULL*)(wc_ptr + (size_t)kk * 256);
                fma2(a0, w2, rh[kk * 4 + 0]); fma2(a1, w2, rh[kk * 4 + 1]);
                fma2(a2, w2, rh[kk * 4 + 2]); fma2(a3, w2, rh[kk * 4 + 3]);
            }
            ULL* dst = PART + (size_t)(kc * 64 + oc) * 4;
            dst[0] = a0; dst[1] = a1; dst[2] = a2; dst[3] = a3;
        }
        __syncthreads();

        // ---- cand combine + tanh (tid < 256) ----
        if (tid < 256) {
            ULL s = add2(add2(add2(PART[(0 * 64 + oc2) * 4 + rc],
                                   PART[(1 * 64 + oc2) * 4 + rc]),
                              add2(PART[(2 * 64 + oc2) * 4 + rc],
                                   PART[(3 * 64 + oc2) * 4 + rc])),
                         add2(add2(PART[(4 * 64 + oc2) * 4 + rc],
                                   PART[(5 * 64 + oc2) * 4 + rc]),
                              add2(PART[(6 * 64 + oc2) * 4 + rc],
                                   PART[(7 * 64 + oc2) * 4 + rc])));
            float s0, s1; unpack2(s, s0, s1);
            ULL c = packf2(tanhf(s0 + xc2.x), tanhf(s1 + xc2.y));
            int gc = cbc + 2 * oc2;
            *(ULL*)&CSf[rc][gc] = c;
            st_dsmem_u64(cs_peer + (unsigned)(rc * 256 + gc) * 4u, c);
        }
        cluster_sync_();   // S2: c (and u) complete in both CTAs

        // ---- update (replicated; bit-identical inputs) ----
        {
#pragma unroll
            for (int p = 0; p < 2; p++) {
                int col = tid & 255;
                int r = (tid >> 8) + 2 * p;
                float u = USf[buf][r][col];
                float c = CSf[r][col];
                float h0, hx; unpack2(HD[col][r], h0, hx);
                float hn = u * h0 + (1.f - u) * c;
                bool v = sv[r] != 0;
                float keep = v ? hn : h0;
                HD[col][r] = dup2(keep);
                if (A.outs && (col >> 7) == role)
                    A.outs[(size_t)((b0 + r) * T + t) * 256 + col] = v ? hn : 0.f;
            }
        }
        __syncthreads();   // HD ready for next step
    }

    // ---- final hidden state (own column half) ----
    if (A.hfin) {
#pragma unroll
        for (int p = 0; p < 2; p++) {
            int col = tid & 255;
            int r = (tid >> 8) + 2 * p;
            if ((col >> 7) == role) {
                float h0, hx; unpack2(HD[col][r], h0, hx);
                A.hfin[(size_t)(b0 + r) * 512 + A.hoff + col] = h0;
            }
        }
    }
    cluster_sync_();   // no CTA exits while peer may still DSMEM-target it
}

// ============================================================================
// Final projection: out[128,4] = [h_head | h_body] @ W_pred + b_pred
// ============================================================================
__global__ void final_pred_kernel(const float* __restrict__ Wp,
                                  const float* __restrict__ bp,
                                  float* __restrict__ out)
{
    int b = threadIdx.x;
    float a0 = bp[0], a1 = bp[1], a2 = bp[2], a3 = bp[3];
    const float* h = g_hcat + (size_t)b * 512;
#pragma unroll 8
    for (int j = 0; j < 512; j++) {
        float hv = h[j];
        float4 w = *(const float4*)(Wp + j * 4);
        a0 += hv * w.x; a1 += hv * w.y; a2 += hv * w.z; a3 += hv * w.w;
    }
    *(float4*)(out + b * 4) = make_float4(a0, a1, a2, a3);
}

// ============================================================================
// Launch
// ============================================================================
extern "C" void kernel_launch(void* const* d_in, const int* in_sizes, int n_in,
                              void* d_out, int out_size)
{
    (void)n_in; (void)out_size;

    const int*   ids_h  = (const int*)d_in[0];
    const int*   ids_b  = (const int*)d_in[1];
    const float* emb    = (const float*)d_in[2];

    const float *hd0_Wg, *hd0_bg, *hd0_Wc, *hd0_bc;
    const float *hd1_Wg, *hd1_bg, *hd1_Wc, *hd1_bc;
    const float *bd0_Wg, *bd0_bg, *bd0_Wc, *bd0_bc;
    const float *bd1_Wg, *bd1_bg, *bd1_Wc, *bd1_bc;
    const float *W_pred, *b_pred;

    if (in_sizes[3] == (2 * HID) * 4 && in_sizes[4] == 4) {
        W_pred = (const float*)d_in[3];
        b_pred = (const float*)d_in[4];
        hd0_Wg = (const float*)d_in[5];  hd0_bg = (const float*)d_in[6];
        hd0_Wc = (const float*)d_in[7];  hd0_bc = (const float*)d_in[8];
        hd1_Wg = (const float*)d_in[9];  hd1_bg = (const float*)d_in[10];
        hd1_Wc = (const float*)d_in[11]; hd1_bc = (const float*)d_in[12];
        bd0_Wg = (const float*)d_in[13]; bd0_bg = (const float*)d_in[14];
        bd0_Wc = (const float*)d_in[15]; bd0_bc = (const float*)d_in[16];
        bd1_Wg = (const float*)d_in[17]; bd1_bg = (const float*)d_in[18];
        bd1_Wc = (const float*)d_in[19]; bd1_bc = (const float*)d_in[20];
    } else {
        hd0_Wg = (const float*)d_in[3];  hd0_bg = (const float*)d_in[4];
        hd0_Wc = (const float*)d_in[5];  hd0_bc = (const float*)d_in[6];
        hd1_Wg = (const float*)d_in[7];  hd1_bg = (const float*)d_in[8];
        hd1_Wc = (const float*)d_in[9];  hd1_bc = (const float*)d_in[10];
        bd0_Wg = (const float*)d_in[11]; bd0_bg = (const float*)d_in[12];
        bd0_Wc = (const float*)d_in[13]; bd0_bc = (const float*)d_in[14];
        bd1_Wg = (const float*)d_in[15]; bd1_bg = (const float*)d_in[16];
        bd1_Wc = (const float*)d_in[17]; bd1_bc = (const float*)d_in[18];
        W_pred = (const float*)d_in[19];
        b_pred = (const float*)d_in[20];
    }

    float* out = (float*)d_out;

    float *XG_h, *XG_b, *out_h, *out_b, *hcat;
    cudaGetSymbolAddress((void**)&XG_h, g_XG_h);
    cudaGetSymbolAddress((void**)&XG_b, g_XG_b);
    cudaGetSymbolAddress((void**)&out_h, g_out_h);
    cudaGetSymbolAddress((void**)&out_b, g_out_b);
    cudaGetSymbolAddress((void**)&hcat, g_hcat);

    const int Mh = BATCH * T_H;
    const int Mb = BATCH * T_B;

    // ---- Layer-0 x-projections (embedding gather fused) ----
    sgemm_kernel<true><<<(Mh / 128) * (512 / 64), 256>>>(
        emb, ids_h, EMB, hd0_Wg, 512, hd0_bg, XG_h, 768, 0,   Mh, 512, EMB);
    sgemm_kernel<true><<<(Mh / 128) * (256 / 64), 256>>>(
        emb, ids_h, EMB, hd0_Wc, 256, hd0_bc, XG_h, 768, 512, Mh, 256, EMB);
    sgemm_kernel<true><<<(Mb / 128) * (512 / 64), 256>>>(
        emb, ids_b, EMB, bd0_Wg, 512, bd0_bg, XG_b, 768, 0,   Mb, 512, EMB);
    sgemm_kernel<true><<<(Mb / 128) * (256 / 64), 256>>>(
        emb, ids_b, EMB, bd0_Wc, 256, bd0_bc, XG_b, 768, 512, Mb, 256, EMB);

    // ---- Layer-0 scan ----
    {
        ScanArgs body = { XG_b, bd0_Wg + (size_t)EMB * 512, bd0_Wc + (size_t)EMB * 256,
                          ids_b, out_b, nullptr, 0, T_B };
        ScanArgs head = { XG_h, hd0_Wg + (size_t)EMB * 512, hd0_Wc + (size_t)EMB * 256,
                          ids_h, out_h, nullptr, 0, T_H };
        gru_scan_cluster<<<128, 512>>>(body, head);
    }

    // ---- Layer-1 x-projections ----
    sgemm_kernel<false><<<(Mh / 128) * (512 / 64), 256>>>(
        out_h, nullptr, HID, hd1_Wg, 512, hd1_bg, XG_h, 768, 0,   Mh, 512, HID);
    sgemm_kernel<false><<<(Mh / 128) * (256 / 64), 256>>>(
        out_h, nullptr, HID, hd1_Wc, 256, hd1_bc, XG_h, 768, 512, Mh, 256, HID);
    sgemm_kernel<false><<<(Mb / 128) * (512 / 64), 256>>>(
        out_b, nullptr, HID, bd1_Wg, 512, bd1_bg, XG_b, 768, 0,   Mb, 512, HID);
    sgemm_kernel<false><<<(Mb / 128) * (256 / 64), 256>>>(
        out_b, nullptr, HID, bd1_Wc, 256, bd1_bc, XG_b, 768, 512, Mb, 256, HID);

    // ---- Layer-1 scan ----
    {
        ScanArgs body = { XG_b, bd1_Wg + (size_t)HID * 512, bd1_Wc + (size_t)HID * 256,
                          ids_b, nullptr, hcat, 256, T_B };
        ScanArgs head = { XG_h, hd1_Wg + (size_t)HID * 512, hd1_Wc + (size_t)HID * 256,
                          ids_h, nullptr, hcat, 0, T_H };
        gru_scan_cluster<<<128, 512>>>(body, head);
    }

    // ---- Final projection ----
    final_pred_kernel<<<1, 128>>>(W_pred, b_pred, out);
}

// round 15
// speedup vs baseline: 1.2797x; 1.1576x over previous
#include <cuda_runtime.h>
#include <math.h>

// Problem constants
#define VOCAB 50000
#define EMB   300
#define HID   256
#define BATCH 128
#define T_H   32
#define T_B   512

typedef unsigned long long ULL;

// -------- scratch (static device allocations; no cudaMalloc anywhere) --------
__device__ float g_XG_h[(size_t)BATCH * T_H * 768];   // headline x-projections [B*T, 768]
__device__ float g_XG_b[(size_t)BATCH * T_B * 768];   // body x-projections
__device__ float g_out_h[(size_t)BATCH * T_H * HID];  // headline layer-0 outputs
__device__ float g_out_b[(size_t)BATCH * T_B * HID];  // body layer-0 outputs
__device__ float g_hcat [(size_t)BATCH * 512];        // [h_head | h_body] final states

// ---- packed f32x2 helpers (fp32-exact) ----
__device__ __forceinline__ void fma2(ULL& d, ULL a, ULL b) {
    asm("fma.rn.f32x2 %0, %1, %2, %0;" : "+l"(d) : "l"(a), "l"(b));
}
__device__ __forceinline__ ULL add2(ULL a, ULL b) {
    ULL d; asm("add.rn.f32x2 %0, %1, %2;" : "=l"(d) : "l"(a), "l"(b)); return d;
}
__device__ __forceinline__ ULL dup2(float x) {
    ULL r; asm("mov.b64 %0, {%1, %1};" : "=l"(r) : "f"(x)); return r;
}
__device__ __forceinline__ ULL packf2(float a, float b) {
    ULL r; asm("mov.b64 %0, {%1, %2};" : "=l"(r) : "f"(a), "f"(b)); return r;
}
__device__ __forceinline__ void unpack2(ULL v, float& a, float& b) {
    asm("mov.b64 {%0, %1}, %2;" : "=f"(a), "=f"(b) : "l"(v));
}

// ---- cluster / DSMEM helpers ----
__device__ __forceinline__ void cluster_sync_() {
    asm volatile("barrier.cluster.arrive.aligned;" ::: "memory");
    asm volatile("barrier.cluster.wait.aligned;" ::: "memory");
}
__device__ __forceinline__ unsigned s2u(const void* p) {
    return (unsigned)__cvta_generic_to_shared(p);
}
__device__ __forceinline__ unsigned mapa_sh(unsigned local, unsigned rank) {
    unsigned r;
    asm("mapa.shared::cluster.u32 %0, %1, %2;" : "=r"(r) : "r"(local), "r"(rank));
    return r;
}
__device__ __forceinline__ void st_dsmem_u64(unsigned addr, ULL v) {
    asm volatile("st.shared::cluster.u64 [%0], %1;" :: "r"(addr), "l"(v) : "memory");
}

// ============================================================================
// Generic SGEMM (unchanged): C[M,N] = A[M,K] @ B[K,N] + bias, row-major.
// ============================================================================
template <bool GATHER>
__global__ __launch_bounds__(256)
void sgemm_kernel(const float* __restrict__ A, const int* __restrict__ ids, int lda,
                  const float* __restrict__ Bm, int ldb,
                  const float* __restrict__ bias,
                  float* __restrict__ C, int ldc, int coff,
                  int M, int N, int K)
{
    const int BM = 128, BN = 64, BK = 8;
    __shared__ float As[BK][BM];
    __shared__ float Bs[BK][BN];

    int nbn = N / BN;
    int bm = blockIdx.x / nbn;
    int bn = blockIdx.x % nbn;
    int tid = threadIdx.x;
    int tx = tid & 15;
    int ty = tid >> 4;

    float acc[8][4];
#pragma unroll
    for (int i = 0; i < 8; i++)
#pragma unroll
        for (int j = 0; j < 4; j++) acc[i][j] = 0.0f;

    int ar = tid >> 1;
    int ak = (tid & 1) * 4;
    int arow = bm * BM + ar;
    const float* arow_ptr;
    if (GATHER) arow_ptr = A + (size_t)ids[arow] * lda;
    else        arow_ptr = A + (size_t)arow * lda;

    int bkr = tid >> 5;
    int bc  = (tid & 31) * 2;
    const float* bptr = Bm + (size_t)bn * BN + bc;

    for (int k0 = 0; k0 < K; k0 += BK) {
        float4 av = make_float4(0.f, 0.f, 0.f, 0.f);
        if (k0 + ak < K) av = *(const float4*)(arow_ptr + k0 + ak);
        float2 bv = make_float2(0.f, 0.f);
        if (k0 + bkr < K) bv = *(const float2*)(bptr + (size_t)(k0 + bkr) * ldb);

        __syncthreads();
        As[ak + 0][ar] = av.x; As[ak + 1][ar] = av.y;
        As[ak + 2][ar] = av.z; As[ak + 3][ar] = av.w;
        Bs[bkr][bc] = bv.x; Bs[bkr][bc + 1] = bv.y;
        __syncthreads();

#pragma unroll
        for (int kk = 0; kk < BK; kk++) {
            float4 b4 = *(const float4*)&Bs[kk][tx * 4];
            float4 a0 = *(const float4*)&As[kk][ty * 8];
            float4 a1 = *(const float4*)&As[kk][ty * 8 + 4];
            float arr[8] = {a0.x, a0.y, a0.z, a0.w, a1.x, a1.y, a1.z, a1.w};
            float brr[4] = {b4.x, b4.y, b4.z, b4.w};
#pragma unroll
            for (int i = 0; i < 8; i++)
#pragma unroll
                for (int j = 0; j < 4; j++)
                    acc[i][j] += arr[i] * brr[j];
        }
    }

    float4 bb = *(const float4*)&bias[bn * BN + tx * 4];
    float bbr[4] = {bb.x, bb.y, bb.z, bb.w};
#pragma unroll
    for (int i = 0; i < 8; i++) {
        int row = bm * BM + ty * 8 + i;
        float4 o;
        o.x = acc[i][0] + bbr[0];
        o.y = acc[i][1] + bbr[1];
        o.z = acc[i][2] + bbr[2];
        o.w = acc[i][3] + bbr[3];
        *(float4*)(C + (size_t)row * ldc + coff + bn * BN + tx * 4) = o;
    }
}

// ============================================================================
// GRU scan, round 15: EXACT R12 structure (cluster(2) + DSMEM, rowpair-packed
// f32x2 state, replicated update) with 1024 threads (32 warps) instead of 512.
// Mainloops deepen to 8 k-splits x 32 k: same instruction count, 2x eligible
// warps and 2x in-flight loads -> halved latency exposure.
//   role 0: r-gates (cols 0..255) + cand cols [0,128)
//   role 1: u-gates (cols 256..511) + cand cols [128,256)
// Static smem ~52 KB (L1D carveout preserved).
// Grid = 128 blocks (64 clusters): [0,64) body, [64,128) head.
// ============================================================================
struct ScanArgs {
    const float* XG;
    const float* Wgh;   // [256,512] k-major h-part of gate weights
    const float* Wch;   // [256,256] k-major h-part of cand weights
    const int*   ids;
    float*       outs;
    float*       hfin;
    int          hoff;
    int          T;
};

__global__ void __cluster_dims__(2, 1, 1) __launch_bounds__(1024)
gru_scan_cluster(ScanArgs body, ScanArgs head)
{
    __shared__ ULL sh_part[4096];       // gate [8][256][2] / cand [8][128][2]  32KB
    __shared__ ULL h_pk [256][2];       // h packed row-pairs                    4KB
    __shared__ ULL rh_pk[256][2];       // r*h packed                            4KB
    __shared__ ULL u_pk[2][256][2];     // u packed, double-buffered             8KB
    __shared__ ULL c_pk[256][2];        // cand packed                           4KB
    __shared__ int sv[4];

    const int bx = blockIdx.x;
    ScanArgs A = (bx < 64) ? body : head;
    const int role = bx & 1;
    const unsigned peer = 1u - (unsigned)role;
    const int pgl = (bx & 63) >> 1;
    const int b0  = pgl * 4;
    const int tid = threadIdx.x;
    const int T = A.T;

    if (tid < 512) ((ULL*)h_pk)[tid] = 0ull;
    __syncthreads();

    const int cb  = role << 8;          // gate col base (0 or 256)
    const int cbc = role << 7;          // cand col base (0 or 128)

    // mainloop mappings: 8 k-splits (32 k each) x 128 owners
    const int ks = tid >> 7;            // 0..7 (uniform per warp)
    const int ow = tid & 127;
    const float* wg = A.Wgh + (size_t)(ks * 32) * 512 + cb + ow * 2;   // 2 gate cols
    const float* wc = A.Wch + (size_t)(ks * 32) * 256 + cbc + ow;      // 1 cand col

    // combine mappings
    const int ccol = tid >> 1, crp = tid & 1;          // gate: 256 cols x 2 rowpairs (tid<512)
    const int dcol = tid >> 1, drp = tid & 1;          // cand: 128 cols x 2 rowpairs (tid<256)
    // update mapping (tid<512)
    const int ucol = tid & 255, urp = (tid >> 8) & 1;

    // peer DSMEM base addresses
    const unsigned rh_peer = mapa_sh(s2u(&rh_pk[0][0]), peer);
    const unsigned u_peer  = mapa_sh(s2u(&u_pk[0][0][0]), peer);
    const unsigned c_peer  = mapa_sh(s2u(&c_pk[0][0]), peer);

    cluster_sync_();   // both CTAs alive before any DSMEM traffic

    for (int t = 0; t < T; t++) {
        const int buf = t & 1;

        // ---- prefetch x-parts + validity ----
        float xg0 = 0.f, xg1 = 0.f;
        if (tid < 512) {
            xg0 = A.XG[(size_t)((b0 + 2 * crp)     * T + t) * 768 + cb + ccol];
            xg1 = A.XG[(size_t)((b0 + 2 * crp + 1) * T + t) * 768 + cb + ccol];
        }
        float xc0 = 0.f, xc1 = 0.f;
        if (tid < 256) {
            xc0 = A.XG[(size_t)((b0 + 2 * drp)     * T + t) * 768 + 512 + cbc + dcol];
            xc1 = A.XG[(size_t)((b0 + 2 * drp + 1) * T + t) * 768 + 512 + cbc + dcol];
        }
        if (tid < 4) sv[tid] = A.ids[(b0 + tid) * T + t];

        // ---- gate mainloop: 2 cols x 2 rowpairs over 32 k ----
        {
            ULL a00 = 0ull, a01 = 0ull, a10 = 0ull, a11 = 0ull;
#pragma unroll 16
            for (int kk = 0; kk < 32; kk++) {
                ULL w2 = *(const ULL*)(wg + (size_t)kk * 512);
                ULL hp0 = h_pk[ks * 32 + kk][0];
                ULL hp1 = h_pk[ks * 32 + kk][1];
                float w0f, w1f; unpack2(w2, w0f, w1f);
                ULL w0 = dup2(w0f), w1 = dup2(w1f);
                fma2(a00, w0, hp0); fma2(a01, w0, hp1);
                fma2(a10, w1, hp0); fma2(a11, w1, hp1);
            }
            ULL* dst = sh_part + (size_t)(ks * 256 + ow * 2) * 2;
            dst[0] = a00; dst[1] = a01; dst[2] = a10; dst[3] = a11;
        }
        __syncthreads();

        // ---- gate combine + sigmoid; role0 -> rh (local+peer), role1 -> u ----
        if (tid < 512) {
            ULL s = add2(add2(add2(sh_part[(0 * 256 + ccol) * 2 + crp],
                                   sh_part[(1 * 256 + ccol) * 2 + crp]),
                              add2(sh_part[(2 * 256 + ccol) * 2 + crp],
                                   sh_part[(3 * 256 + ccol) * 2 + crp])),
                         add2(add2(sh_part[(4 * 256 + ccol) * 2 + crp],
                                   sh_part[(5 * 256 + ccol) * 2 + crp]),
                              add2(sh_part[(6 * 256 + ccol) * 2 + crp],
                                   sh_part[(7 * 256 + ccol) * 2 + crp])));
            float s0, s1; unpack2(s, s0, s1);
            float g0 = 1.f / (1.f + expf(-(s0 + xg0)));
            float g1 = 1.f / (1.f + expf(-(s1 + xg1)));
            if (role == 0) {
                float h0, h1; unpack2(h_pk[ccol][crp], h0, h1);
                ULL rh = packf2(g0 * h0, g1 * h1);
                rh_pk[ccol][crp] = rh;
                st_dsmem_u64(rh_peer + (unsigned)(ccol * 2 + crp) * 8u, rh);
            } else {
                ULL u = packf2(g0, g1);
                u_pk[buf][ccol][crp] = u;
                st_dsmem_u64(u_peer + (unsigned)((buf * 256 + ccol) * 2 + crp) * 8u, u);
            }
        }
        cluster_sync_();   // S1: rh visible in both CTAs (u already en route)

        // ---- cand mainloop: 1 col x 2 rowpairs over 32 k ----
        {
            ULL c0a = 0ull, c1a = 0ull;
#pragma unroll 16
            for (int kk = 0; kk < 32; kk++) {
                float w = wc[(size_t)kk * 256];
                ULL wd = dup2(w);
                fma2(c0a, wd, rh_pk[ks * 32 + kk][0]);
                fma2(c1a, wd, rh_pk[ks * 32 + kk][1]);
            }
            sh_part[(ks * 128 + ow) * 2 + 0] = c0a;
            sh_part[(ks * 128 + ow) * 2 + 1] = c1a;
        }
        __syncthreads();

        // ---- cand combine + tanh (tid < 256); own half local + peer ----
        if (tid < 256) {
            ULL s = add2(add2(add2(sh_part[(0 * 128 + dcol) * 2 + drp],
                                   sh_part[(1 * 128 + dcol) * 2 + drp]),
                              add2(sh_part[(2 * 128 + dcol) * 2 + drp],
                                   sh_part[(3 * 128 + dcol) * 2 + drp])),
                         add2(add2(sh_part[(4 * 128 + dcol) * 2 + drp],
                                   sh_part[(5 * 128 + dcol) * 2 + drp]),
                              add2(sh_part[(6 * 128 + dcol) * 2 + drp],
                                   sh_part[(7 * 128 + dcol) * 2 + drp])));
            float s0, s1; unpack2(s, s0, s1);
            ULL c = packf2(tanhf(s0 + xc0), tanhf(s1 + xc1));
            int gc = cbc + dcol;
            c_pk[gc][drp] = c;
            st_dsmem_u64(c_peer + (unsigned)(gc * 2 + drp) * 8u, c);
        }
        cluster_sync_();   // S2: c complete in both CTAs

        // ---- update (replicated in both CTAs; bit-identical inputs) ----
        if (tid < 512) {
            float u0, u1, c0, c1, h0, h1;
            unpack2(u_pk[buf][ucol][urp], u0, u1);
            unpack2(c_pk[ucol][urp],      c0, c1);
            unpack2(h_pk[ucol][urp],      h0, h1);
            float hn0 = u0 * h0 + (1.f - u0) * c0;
            float hn1 = u1 * h1 + (1.f - u1) * c1;
            bool v0 = sv[2 * urp] != 0, v1 = sv[2 * urp + 1] != 0;
            h_pk[ucol][urp] = packf2(v0 ? hn0 : h0, v1 ? hn1 : h1);
            if (A.outs && (ucol >> 7) == role) {
                A.outs[(size_t)((b0 + 2 * urp)     * T + t) * 256 + ucol] = v0 ? hn0 : 0.f;
                A.outs[(size_t)((b0 + 2 * urp + 1) * T + t) * 256 + ucol] = v1 ? hn1 : 0.f;
            }
        }
        __syncthreads();   // h_pk ready for next gate mainloop
    }

    // ---- final hidden state (own column half) ----
    if (A.hfin && tid < 512 && (ucol >> 7) == role) {
        float k0, k1; unpack2(h_pk[ucol][urp], k0, k1);
        A.hfin[(size_t)(b0 + 2 * urp)     * 512 + A.hoff + ucol] = k0;
        A.hfin[(size_t)(b0 + 2 * urp + 1) * 512 + A.hoff + ucol] = k1;
    }
    cluster_sync_();   // no CTA exits while peer may still DSMEM-target it
}

// ============================================================================
// Final projection: out[128,4] = [h_head | h_body] @ W_pred + b_pred
// ============================================================================
__global__ void final_pred_kernel(const float* __restrict__ Wp,
                                  const float* __restrict__ bp,
                                  float* __restrict__ out)
{
    int b = threadIdx.x;
    float a0 = bp[0], a1 = bp[1], a2 = bp[2], a3 = bp[3];
    const float* h = g_hcat + (size_t)b * 512;
#pragma unroll 8
    for (int j = 0; j < 512; j++) {
        float hv = h[j];
        float4 w = *(const float4*)(Wp + j * 4);
        a0 += hv * w.x; a1 += hv * w.y; a2 += hv * w.z; a3 += hv * w.w;
    }
    *(float4*)(out + b * 4) = make_float4(a0, a1, a2, a3);
}

// ============================================================================
// Launch
// ============================================================================
extern "C" void kernel_launch(void* const* d_in, const int* in_sizes, int n_in,
                              void* d_out, int out_size)
{
    (void)n_in; (void)out_size;

    const int*   ids_h  = (const int*)d_in[0];
    const int*   ids_b  = (const int*)d_in[1];
    const float* emb    = (const float*)d_in[2];

    const float *hd0_Wg, *hd0_bg, *hd0_Wc, *hd0_bc;
    const float *hd1_Wg, *hd1_bg, *hd1_Wc, *hd1_bc;
    const float *bd0_Wg, *bd0_bg, *bd0_Wc, *bd0_bc;
    const float *bd1_Wg, *bd1_bg, *bd1_Wc, *bd1_bc;
    const float *W_pred, *b_pred;

    if (in_sizes[3] == (2 * HID) * 4 && in_sizes[4] == 4) {
        W_pred = (const float*)d_in[3];
        b_pred = (const float*)d_in[4];
        hd0_Wg = (const float*)d_in[5];  hd0_bg = (const float*)d_in[6];
        hd0_Wc = (const float*)d_in[7];  hd0_bc = (const float*)d_in[8];
        hd1_Wg = (const float*)d_in[9];  hd1_bg = (const float*)d_in[10];
        hd1_Wc = (const float*)d_in[11]; hd1_bc = (const float*)d_in[12];
        bd0_Wg = (const float*)d_in[13]; bd0_bg = (const float*)d_in[14];
        bd0_Wc = (const float*)d_in[15]; bd0_bc = (const float*)d_in[16];
        bd1_Wg = (const float*)d_in[17]; bd1_bg = (const float*)d_in[18];
        bd1_Wc = (const float*)d_in[19]; bd1_bc = (const float*)d_in[20];
    } else {
        hd0_Wg = (const float*)d_in[3];  hd0_bg = (const float*)d_in[4];
        hd0_Wc = (const float*)d_in[5];  hd0_bc = (const float*)d_in[6];
        hd1_Wg = (const float*)d_in[7];  hd1_bg = (const float*)d_in[8];
        hd1_Wc = (const float*)d_in[9];  hd1_bc = (const float*)d_in[10];
        bd0_Wg = (const float*)d_in[11]; bd0_bg = (const float*)d_in[12];
        bd0_Wc = (const float*)d_in[13]; bd0_bc = (const float*)d_in[14];
        bd1_Wg = (const float*)d_in[15]; bd1_bg = (const float*)d_in[16];
        bd1_Wc = (const float*)d_in[17]; bd1_bc = (const float*)d_in[18];
        W_pred = (const float*)d_in[19];
        b_pred = (const float*)d_in[20];
    }

    float* out = (float*)d_out;

    float *XG_h, *XG_b, *out_h, *out_b, *hcat;
    cudaGetSymbolAddress((void**)&XG_h, g_XG_h);
    cudaGetSymbolAddress((void**)&XG_b, g_XG_b);
    cudaGetSymbolAddress((void**)&out_h, g_out_h);
    cudaGetSymbolAddress((void**)&out_b, g_out_b);
    cudaGetSymbolAddress((void**)&hcat, g_hcat);

    const int Mh = BATCH * T_H;
    const int Mb = BATCH * T_B;

    // ---- Layer-0 x-projections (embedding gather fused) ----
    sgemm_kernel<true><<<(Mh / 128) * (512 / 64), 256>>>(
        emb, ids_h, EMB, hd0_Wg, 512, hd0_bg, XG_h, 768, 0,   Mh, 512, EMB);
    sgemm_kernel<true><<<(Mh / 128) * (256 / 64), 256>>>(
        emb, ids_h, EMB, hd0_Wc, 256, hd0_bc, XG_h, 768, 512, Mh, 256, EMB);
    sgemm_kernel<true><<<(Mb / 128) * (512 / 64), 256>>>(
        emb, ids_b, EMB, bd0_Wg, 512, bd0_bg, XG_b, 768, 0,   Mb, 512, EMB);
    sgemm_kernel<true><<<(Mb / 128) * (256 / 64), 256>>>(
        emb, ids_b, EMB, bd0_Wc, 256, bd0_bc, XG_b, 768, 512, Mb, 256, EMB);

    // ---- Layer-0 scan ----
    {
        ScanArgs body = { XG_b, bd0_Wg + (size_t)EMB * 512, bd0_Wc + (size_t)EMB * 256,
                          ids_b, out_b, nullptr, 0, T_B };
        ScanArgs head = { XG_h, hd0_Wg + (size_t)EMB * 512, hd0_Wc + (size_t)EMB * 256,
                          ids_h, out_h, nullptr, 0, T_H };
        gru_scan_cluster<<<128, 1024>>>(body, head);
    }

    // ---- Layer-1 x-projections ----
    sgemm_kernel<false><<<(Mh / 128) * (512 / 64), 256>>>(
        out_h, nullptr, HID, hd1_Wg, 512, hd1_bg, XG_h, 768, 0,   Mh, 512, HID);
    sgemm_kernel<false><<<(Mh / 128) * (256 / 64), 256>>>(
        out_h, nullptr, HID, hd1_Wc, 256, hd1_bc, XG_h, 768, 512, Mh, 256, HID);
    sgemm_kernel<false><<<(Mb / 128) * (512 / 64), 256>>>(
        out_b, nullptr, HID, bd1_Wg, 512, bd1_bg, XG_b, 768, 0,   Mb, 512, HID);
    sgemm_kernel<false><<<(Mb / 128) * (256 / 64), 256>>>(
        out_b, nullptr, HID, bd1_Wc, 256, bd1_bc, XG_b, 768, 512, Mb, 256, HID);

    // ---- Layer-1 scan ----
    {
        ScanArgs body = { XG_b, bd1_Wg + (size_t)HID * 512, bd1_Wc + (size_t)HID * 256,
                          ids_b, nullptr, hcat, 256, T_B };
        ScanArgs head = { XG_h, hd1_Wg + (size_t)HID * 512, hd1_Wc + (size_t)HID * 256,
                          ids_h, nullptr, hcat, 0, T_H };
        gru_scan_cluster<<<128, 1024>>>(body, head);
    }

    // ---- Final projection ----
    final_pred_kernel<<<1, 128>>>(W_pred, b_pred, out);
}